// round 16
// baseline (speedup 1.0000x reference)
#include <cuda_runtime.h>
#include <cuda_fp16.h>
#include <math.h>
#include <stdint.h>

// ---------------- problem constants ----------------
#define NTOK 4096      // B*T
#define TSEQ 2048
#define HIDD 2048
#define NH   16
#define DHEAD 128
#define RROT 32
#define D_CQ 768
#define D_CKV 512
#define D_CO 512
#define D_QKVS 1280    // D_CQ + D_CKV
#define QK_SCALE 0.08838834764831845f  // 128^-0.5

// ---------------- scratch ----------------
__device__ float g_qskvs[(size_t)NTOK * D_QKVS];   // qs | kvs (fp32, pre-rms)
__device__ float g_o[(size_t)NTOK * D_CO];
__device__ __half g_xh[(size_t)NTOK * HIDD];
__device__ __half g_qsh[(size_t)NTOK * D_CQ];
__device__ __half g_kvsh[(size_t)NTOK * D_CKV];
__device__ __half g_qh[(size_t)NTOK * 2048];
__device__ __half g_kvh[(size_t)NTOK * 4096];   // k | v
__device__ __half g_gatesh[(size_t)NTOK * 2048];
__device__ __half g_attnh[(size_t)NTOK * 2048];
__device__ __half g_oh[(size_t)NTOK * D_CO];
__device__ __half g_wqkvs_h[(size_t)D_QKVS * HIDD];  // wqs | wkvs
__device__ __half g_wqp_h[(size_t)2048 * D_CQ];
__device__ __half g_wkvp_h[(size_t)4096 * D_CKV];
__device__ __half g_wgp_h[(size_t)2048 * HIDD];
__device__ __half g_wop_h[(size_t)D_CO * 2048];
__device__ __half g_wos_h[(size_t)HIDD * D_CO];

// ---------------- helpers ----------------
__device__ __forceinline__ uint32_t smem_u32(const void* p) {
    uint32_t a;
    asm("{ .reg .u64 t; cvta.to.shared.u64 t, %1; cvt.u32.u64 %0, t; }" : "=r"(a) : "l"(p));
    return a;
}
__device__ __forceinline__ void mma16(float c[4], const uint32_t a[4], uint32_t b0, uint32_t b1) {
    asm volatile(
        "mma.sync.aligned.m16n8k16.row.col.f32.f16.f16.f32 "
        "{%0,%1,%2,%3},{%4,%5,%6,%7},{%8,%9},{%0,%1,%2,%3};"
        : "+f"(c[0]), "+f"(c[1]), "+f"(c[2]), "+f"(c[3])
        : "r"(a[0]), "r"(a[1]), "r"(a[2]), "r"(a[3]), "r"(b0), "r"(b1));
}
__device__ __forceinline__ void ldsm4(uint32_t* r, uint32_t a) {
    asm volatile("ldmatrix.sync.aligned.m8n8.x4.shared.b16 {%0,%1,%2,%3}, [%4];"
        : "=r"(r[0]), "=r"(r[1]), "=r"(r[2]), "=r"(r[3]) : "r"(a));
}
__device__ __forceinline__ void ldsm4t(uint32_t* r, uint32_t a) {
    asm volatile("ldmatrix.sync.aligned.m8n8.x4.trans.shared.b16 {%0,%1,%2,%3}, [%4];"
        : "=r"(r[0]), "=r"(r[1]), "=r"(r[2]), "=r"(r[3]) : "r"(a));
}
__device__ __forceinline__ void cpa16(uint32_t saddr, const void* g) {
    asm volatile("cp.async.cg.shared.global [%0], [%1], 16;" :: "r"(saddr), "l"(g));
}
#define CPA_COMMIT() asm volatile("cp.async.commit_group;" ::: "memory")
#define CPA_WAIT(n)  asm volatile("cp.async.wait_group %0;" :: "n"(n) : "memory")

// ---------------- merged fp32 -> fp16 convert (x + 7 weights) -------------
#define CV_P1 8388608u
#define CV_P2 (CV_P1 + 1572864u)
#define CV_P3 (CV_P2 + 1048576u)
#define CV_P4 (CV_P3 + 1572864u)
#define CV_P5 (CV_P4 + 2097152u)
#define CV_P6 (CV_P5 + 4194304u)
#define CV_P7 (CV_P6 + 1048576u)
#define CV_END (CV_P7 + 1048576u)
#define CV_BLOCKS (CV_END / 1024)

__global__ void cvt_all(
    const float* __restrict__ s0, const float* __restrict__ s1,
    const float* __restrict__ s2, const float* __restrict__ s3,
    const float* __restrict__ s4, const float* __restrict__ s5,
    const float* __restrict__ s6, const float* __restrict__ s7,
    __half* __restrict__ d0, __half* __restrict__ d1,
    __half* __restrict__ d2, __half* __restrict__ d3,
    __half* __restrict__ d4, __half* __restrict__ d5,
    __half* __restrict__ d6, __half* __restrict__ d7)
{
    uint32_t i = (blockIdx.x * 256 + threadIdx.x) * 4;
    const float* s; __half* d; uint32_t off;
    if      (i < CV_P1) { s = s0; d = d0; off = i; }
    else if (i < CV_P2) { s = s1; d = d1; off = i - CV_P1; }
    else if (i < CV_P3) { s = s2; d = d2; off = i - CV_P2; }
    else if (i < CV_P4) { s = s3; d = d3; off = i - CV_P3; }
    else if (i < CV_P5) { s = s4; d = d4; off = i - CV_P4; }
    else if (i < CV_P6) { s = s5; d = d5; off = i - CV_P5; }
    else if (i < CV_P7) { s = s6; d = d6; off = i - CV_P6; }
    else                { s = s7; d = d7; off = i - CV_P7; }
    float4 v = *(const float4*)(s + off);
    __half2* o = (__half2*)(d + off);
    o[0] = __floats2half2_rn(v.x, v.y);
    o[1] = __floats2half2_rn(v.z, v.w);
}

// ---------------- fp16 GEMM 128x128 (verified R8) --------------------------
#define GH_SMEM_BYTES (3 * 16384)

template <int MODE>
__global__ __launch_bounds__(256, 2) void gemm_h(
    const __half* __restrict__ A, const __half* __restrict__ B, void* __restrict__ Cv,
    int N, int K,
    const float* __restrict__ cosT, const float* __restrict__ sinT,
    const __half* __restrict__ gates)
{
    extern __shared__ char hsm[];
    const uint32_t shb = smem_u32(hsm);
    const int tid = threadIdx.x, lane = tid & 31, w = tid >> 5;
    const int g = lane >> 2, tig = lane & 3;
    const int wm = (w & 3) * 32, wn = (w >> 2) * 64;
    const int bm = blockIdx.y * 128, bn = blockIdx.x * 128;
    const int lr = lane & 15, lc = lane >> 4;

    float acc[2][8][4];
#pragma unroll
    for (int mt = 0; mt < 2; mt++)
#pragma unroll
        for (int nt = 0; nt < 8; nt++)
#pragma unroll
            for (int r = 0; r < 4; r++) acc[mt][nt][r] = 0.f;

    const int srow = tid >> 1, shalf = tid & 1;
    const __half* pa = A + (size_t)(bm + srow) * K + shalf * 16;
    const __half* pb = B + (size_t)(bn + srow) * K + shalf * 16;
    const uint32_t da0 = srow * 64 + ((((shalf * 2 + 0) + (srow >> 1)) & 3) << 4);
    const uint32_t da1 = srow * 64 + ((((shalf * 2 + 1) + (srow >> 1)) & 3) << 4);

    const int ntile = K >> 5;
#define GH_ISSUE(t) do {                                       \
        uint32_t _b = shb + ((t) % 3) * 16384;                 \
        const __half* _a = pa + (size_t)(t) * 32;              \
        const __half* _bb = pb + (size_t)(t) * 32;             \
        cpa16(_b + da0, _a);                                   \
        cpa16(_b + da1, _a + 8);                               \
        cpa16(_b + 8192 + da0, _bb);                           \
        cpa16(_b + 8192 + da1, _bb + 8);                       \
        CPA_COMMIT();                                          \
    } while (0)

    GH_ISSUE(0);
    GH_ISSUE(1);

    for (int i = 0; i < ntile; i++) {
        if (i < ntile - 1) { CPA_WAIT(1); } else { CPA_WAIT(0); }
        __syncthreads();
        if (i + 2 < ntile) GH_ISSUE(i + 2);
        const uint32_t base = shb + (i % 3) * 16384;
#pragma unroll
        for (int ks = 0; ks < 2; ks++) {
            const int cb = 2 * ks + lc;
            uint32_t af[2][4], bf[4][4];
#pragma unroll
            for (int mt = 0; mt < 2; mt++) {
                int r = wm + mt * 16 + lr;
                ldsm4(af[mt], base + r * 64 + (((cb + (r >> 1)) & 3) << 4));
            }
#pragma unroll
            for (int p = 0; p < 4; p++) {
                int r = wn + p * 16 + lr;
                ldsm4(bf[p], base + 8192 + r * 64 + (((cb + (r >> 1)) & 3) << 4));
            }
#pragma unroll
            for (int mt = 0; mt < 2; mt++)
#pragma unroll
                for (int nt = 0; nt < 8; nt++) {
                    int p = nt >> 1, s = nt & 1;
                    mma16(acc[mt][nt], af[mt], bf[p][s], bf[p][s + 2]);
                }
        }
        __syncthreads();
    }

    if ((MODE == 2 || (MODE == 3 && bn < 2048)) && wn == 0) {
#pragma unroll
        for (int mt = 0; mt < 2; mt++) {
            int r0 = bm + wm + mt * 16 + g;
            int t0 = r0 & (TSEQ - 1), t1 = (r0 + 8) & (TSEQ - 1);
#pragma unroll
            for (int nt = 0; nt < 2; nt++) {
                int d = nt * 8 + 2 * tig;
                float c0a = cosT[t0 * RROT + d],      c0b = cosT[t0 * RROT + d + 1];
                float c0c = cosT[t0 * RROT + d + 16], c0d = cosT[t0 * RROT + d + 17];
                float s0a = sinT[t0 * RROT + d],      s0b = sinT[t0 * RROT + d + 1];
                float s0c = sinT[t0 * RROT + d + 16], s0d = sinT[t0 * RROT + d + 17];
                float c1a = cosT[t1 * RROT + d],      c1b = cosT[t1 * RROT + d + 1];
                float c1c = cosT[t1 * RROT + d + 16], c1d = cosT[t1 * RROT + d + 17];
                float s1a = sinT[t1 * RROT + d],      s1b = sinT[t1 * RROT + d + 1];
                float s1c = sinT[t1 * RROT + d + 16], s1d = sinT[t1 * RROT + d + 17];
                float x, y;
                x = acc[mt][nt][0]; y = acc[mt][nt + 2][0];
                acc[mt][nt][0] = x * c0a - y * s0a; acc[mt][nt + 2][0] = y * c0c + x * s0c;
                x = acc[mt][nt][1]; y = acc[mt][nt + 2][1];
                acc[mt][nt][1] = x * c0b - y * s0b; acc[mt][nt + 2][1] = y * c0d + x * s0d;
                x = acc[mt][nt][2]; y = acc[mt][nt + 2][2];
                acc[mt][nt][2] = x * c1a - y * s1a; acc[mt][nt + 2][2] = y * c1c + x * s1c;
                x = acc[mt][nt][3]; y = acc[mt][nt + 2][3];
                acc[mt][nt][3] = x * c1b - y * s1b; acc[mt][nt + 2][3] = y * c1d + x * s1d;
            }
        }
    }
    if (MODE == 3 && bn >= 2048) {
#pragma unroll
        for (int mt = 0; mt < 2; mt++) {
            int r0 = bm + wm + mt * 16 + g;
#pragma unroll
            for (int nt = 0; nt < 8; nt++) {
                int cg = bn - 2048 + wn + nt * 8 + 2 * tig;
                __half2 ga = *(const __half2*)(gates + (size_t)r0 * 2048 + cg);
                __half2 gb = *(const __half2*)(gates + (size_t)(r0 + 8) * 2048 + cg);
                float g0 = __low2float(ga), g1 = __high2float(ga);
                float g2 = __low2float(gb), g3 = __high2float(gb);
                acc[mt][nt][0] *= g0 / (1.f + __expf(-g0));
                acc[mt][nt][1] *= g1 / (1.f + __expf(-g1));
                acc[mt][nt][2] *= g2 / (1.f + __expf(-g2));
                acc[mt][nt][3] *= g3 / (1.f + __expf(-g3));
            }
        }
    }

#pragma unroll
    for (int mt = 0; mt < 2; mt++) {
        int r0 = bm + wm + mt * 16 + g;
#pragma unroll
        for (int nt = 0; nt < 8; nt++) {
            int c0 = bn + wn + nt * 8 + 2 * tig;
            if (MODE == 0) {
                float* C = (float*)Cv;
                *(float2*)(C + (size_t)r0 * N + c0)       = make_float2(acc[mt][nt][0], acc[mt][nt][1]);
                *(float2*)(C + (size_t)(r0 + 8) * N + c0) = make_float2(acc[mt][nt][2], acc[mt][nt][3]);
            } else {
                __half* C = (__half*)Cv;
                *(__half2*)(C + (size_t)r0 * N + c0)       = __floats2half2_rn(acc[mt][nt][0], acc[mt][nt][1]);
                *(__half2*)(C + (size_t)(r0 + 8) * N + c0) = __floats2half2_rn(acc[mt][nt][2], acc[mt][nt][3]);
            }
        }
    }
}

// ---------------- fp16 GEMM 64x128, 128 threads, 4 CTAs/SM -----------------
#define G64_STG 12288
#define G64_SMEM_BYTES (3 * G64_STG)

__global__ __launch_bounds__(128, 4) void gemm64(
    const __half* __restrict__ A, const __half* __restrict__ B, float* __restrict__ C,
    int N, int K)
{
    extern __shared__ char hsm[];
    const uint32_t shb = smem_u32(hsm);
    const int tid = threadIdx.x, lane = tid & 31, w = tid >> 5;
    const int g = lane >> 2, tig = lane & 3;
    const int wm = (w & 1) * 32, wn = (w >> 1) * 64;
    const int bm = blockIdx.y * 64, bn = blockIdx.x * 128;
    const int lr = lane & 15, lc = lane >> 4;

    float acc[2][8][4];
#pragma unroll
    for (int mt = 0; mt < 2; mt++)
#pragma unroll
        for (int nt = 0; nt < 8; nt++)
#pragma unroll
            for (int r = 0; r < 4; r++) acc[mt][nt][r] = 0.f;

    const int ntile = K >> 5;
#define G64_ISSUE(t) do {                                                        \
        uint32_t _b = shb + ((t) % 3) * G64_STG;                                 \
        _Pragma("unroll")                                                        \
        for (int _j = 0; _j < 6; _j++) {                                         \
            int _f = _j * 128 + tid;                                             \
            int _r = _f >> 2, _c = _f & 3;                                       \
            uint32_t _d = _b + _r * 64 + (((_c + (_r >> 1)) & 3) << 4);          \
            const __half* _g = (_r < 64)                                         \
                ? A + (size_t)(bm + _r) * K + (size_t)(t) * 32 + _c * 8          \
                : B + (size_t)(bn + _r - 64) * K + (size_t)(t) * 32 + _c * 8;    \
            cpa16(_d, _g);                                                       \
        }                                                                        \
        CPA_COMMIT();                                                            \
    } while (0)

    G64_ISSUE(0);
    G64_ISSUE(1);

    for (int i = 0; i < ntile; i++) {
        if (i < ntile - 1) { CPA_WAIT(1); } else { CPA_WAIT(0); }
        __syncthreads();
        if (i + 2 < ntile) G64_ISSUE(i + 2);
        const uint32_t base = shb + (i % 3) * G64_STG;
#pragma unroll
        for (int ks = 0; ks < 2; ks++) {
            const int cb = 2 * ks + lc;
            uint32_t af[2][4], bf[4][4];
#pragma unroll
            for (int mt = 0; mt < 2; mt++) {
                int r = wm + mt * 16 + lr;
                ldsm4(af[mt], base + r * 64 + (((cb + (r >> 1)) & 3) << 4));
            }
#pragma unroll
            for (int p = 0; p < 4; p++) {
                int r = 64 + wn + p * 16 + lr;
                ldsm4(bf[p], base + r * 64 + (((cb + (r >> 1)) & 3) << 4));
            }
#pragma unroll
            for (int mt = 0; mt < 2; mt++)
#pragma unroll
                for (int nt = 0; nt < 8; nt++) {
                    int p = nt >> 1, s = nt & 1;
                    mma16(acc[mt][nt], af[mt], bf[p][s], bf[p][s + 2]);
                }
        }
        __syncthreads();
    }

#pragma unroll
    for (int mt = 0; mt < 2; mt++) {
        int r0 = bm + wm + mt * 16 + g;
#pragma unroll
        for (int nt = 0; nt < 8; nt++) {
            int c0 = bn + wn + nt * 8 + 2 * tig;
            *(float2*)(C + (size_t)r0 * N + c0)       = make_float2(acc[mt][nt][0], acc[mt][nt][1]);
            *(float2*)(C + (size_t)(r0 + 8) * N + c0) = make_float2(acc[mt][nt][2], acc[mt][nt][3]);
        }
    }
}

// ---------------- RMSNorm (vectorized, paired segments) --------------------
__global__ void rms2(const float* __restrict__ X,
                     const float* __restrict__ w0, const float* __restrict__ w1,
                     int D0, int D1, int strideX,
                     __half* __restrict__ H0, __half* __restrict__ H1)
{
    __shared__ float red[8];
    const int row = blockIdx.x, tid = threadIdx.x;
    const int lane = tid & 31, wid = tid >> 5;
    const int which = blockIdx.y;
    const int D = which ? D1 : D0;
    const float* w = which ? w1 : w0;
    const float4* x = (const float4*)(X + (size_t)row * strideX + (which ? D0 : 0));
    __half* hh = (which ? H1 : H0) + (size_t)row * D;
    const int D4 = D >> 2;
    float ss = 0.f;
    for (int i = tid; i < D4; i += 256) {
        float4 v = x[i];
        ss += v.x * v.x + v.y * v.y + v.z * v.z + v.w * v.w;
    }
#pragma unroll
    for (int m = 16; m > 0; m >>= 1) ss += __shfl_xor_sync(0xffffffff, ss, m);
    if (lane == 0) red[wid] = ss;
    __syncthreads();
    float tot = 0.f;
#pragma unroll
    for (int j = 0; j < 8; j++) tot += red[j];
    float inv = rsqrtf(tot / (float)D + 1e-6f);
    for (int i = tid; i < D4; i += 256) {
        float4 v = x[i];
        float4 ww = *(const float4*)(w + i * 4);
        __half2* dst = (__half2*)(hh + i * 4);
        dst[0] = __floats2half2_rn(ww.x * (v.x * inv), ww.y * (v.y * inv));
        dst[1] = __floats2half2_rn(ww.z * (v.z * inv), ww.w * (v.w * inv));
    }
}

// ---------------- flash64: 64q blocks, dv-split warps, 2 CTAs/SM -----------
// 256 threads = 8 warps: qg = w&3 (16 q rows each), wc = w>>2 (k/dv half).
// smem bytes: Q 17408 | KV 4*17408 | P 9216 | stats 1536 = 97792
#define F64_QB   17408u
#define F64_KVB  17408u
#define F64_P_OFF  (F64_QB + 4 * F64_KVB)          // 87040 (bytes)
#define F64_ST_OFF (F64_P_OFF + 9216u)             // 96256 (bytes)
#define F64_SMEM_BYTES (F64_ST_OFF + 1536u)        // 97792

__global__ __launch_bounds__(256, 2) void flash64(
    const __half* __restrict__ Qh, const __half* __restrict__ KVh, __half* __restrict__ O)
{
    extern __shared__ __half sh2[];
    const uint32_t qbs = smem_u32(sh2);
    const uint32_t kvb0 = qbs + F64_QB;
    const uint32_t kvb1 = qbs + F64_QB + 2 * F64_KVB;
    const uint32_t pbs = qbs + F64_P_OFF;
    // NOTE: byte arithmetic! (R15 bug was __half* + byte-offset)
    __half* Ps  = (__half*)((char*)sh2 + F64_P_OFF);
    float* Mrow = (float*)((char*)sh2 + F64_ST_OFF);   // [64]
    float* Lrow = Mrow + 64;
    float* pmax = Lrow + 64;    // [2][64]
    float* psum = pmax + 128;   // [2][64]

    const int qt = (int)gridDim.x - 1 - blockIdx.x;   // LPT
    const int h = blockIdx.y, b = blockIdx.z;
    const int tid = threadIdx.x, lane = tid & 31, w = tid >> 5;
    const int g = lane >> 2, tig = lane & 3;
    const int lr = lane & 15, lc = lane >> 4;
    const int qg = w & 3, wc = w >> 2;
    const size_t qbase = (size_t)b * TSEQ + qt * 64;
    const size_t kvrow = (size_t)b * TSEQ;

#define F64_KV_ISSUE(kt) do {                                                    \
        const uint32_t _kb = ((kt) & 1) ? kvb1 : kvb0;                           \
        const __half* _base = KVh + (kvrow + (size_t)(kt) * 64) * 4096 + h * 128;\
        _Pragma("unroll")                                                        \
        for (int _j = 0; _j < 4; _j++) {                                         \
            int _f = tid * 4 + _j;                                               \
            int _r = _f >> 4, _c = _f & 15;                                      \
            uint32_t _d = _r * 272 + _c * 16;                                    \
            cpa16(_kb + _d,           _base + (size_t)_r * 4096 + _c * 8);       \
            cpa16(_kb + F64_KVB + _d, _base + (size_t)_r * 4096 + 2048 + _c * 8);\
        }                                                                        \
        CPA_COMMIT();                                                            \
    } while (0)

    // stage Q (64 rows) + first KV tile
#pragma unroll
    for (int j = 0; j < 4; j++) {
        int f = tid * 4 + j;
        int r = f >> 4, c = f & 15;
        cpa16(qbs + r * 272 + c * 16, Qh + (qbase + r) * 2048 + h * 128 + c * 8);
    }
    CPA_COMMIT();
    F64_KV_ISSUE(0);
    if (tid < 64) { Mrow[tid] = -1e30f; Lrow[tid] = 0.f; }
    CPA_WAIT(1);        // Q complete

    float o[8][4];
#pragma unroll
    for (int nt = 0; nt < 8; nt++)
#pragma unroll
        for (int r = 0; r < 4; r++) o[nt][r] = 0.f;

    const int r0 = qg * 16 + g, r1 = r0 + 8;

    const int nkt = qt + 1;
    for (int kt = 0; kt < nkt; kt++) {
        if (kt + 1 < nkt) { F64_KV_ISSUE(kt + 1); CPA_WAIT(1); }
        else              { CPA_WAIT(0); }
        __syncthreads();
        const uint32_t kbs = (kt & 1) ? kvb1 : kvb0;
        const uint32_t vbs = kbs + F64_KVB;

        // ---- S: 16q x 32k (this warp's k half) ----
        float s[4][4];
#pragma unroll
        for (int nt = 0; nt < 4; nt++)
#pragma unroll
            for (int r = 0; r < 4; r++) s[nt][r] = 0.f;
#pragma unroll
        for (int ks = 0; ks < 8; ks++) {
            uint32_t qf[4], bf[2][4];
            ldsm4(qf, qbs + (qg * 16 + lr) * 272 + (2 * ks + lc) * 16);
#pragma unroll
            for (int p = 0; p < 2; p++)
                ldsm4(bf[p], kbs + (wc * 32 + p * 16 + lr) * 272 + (2 * ks + lc) * 16);
#pragma unroll
            for (int nt = 0; nt < 4; nt++)
                mma16(s[nt], qf, bf[nt >> 1][nt & 1], bf[nt >> 1][(nt & 1) + 2]);
        }

        // ---- scale + mask + partial row max ----
        const int qg0 = qt * 64 + r0, qg1 = qg0 + 8;
        float mx0 = -1e30f, mx1 = -1e30f;
#pragma unroll
        for (int nt = 0; nt < 4; nt++) {
            int kg0 = kt * 64 + wc * 32 + nt * 8 + 2 * tig, kg1 = kg0 + 1;
            s[nt][0] = (kg0 <= qg0) ? s[nt][0] * QK_SCALE : -1e30f;
            s[nt][1] = (kg1 <= qg0) ? s[nt][1] * QK_SCALE : -1e30f;
            s[nt][2] = (kg0 <= qg1) ? s[nt][2] * QK_SCALE : -1e30f;
            s[nt][3] = (kg1 <= qg1) ? s[nt][3] * QK_SCALE : -1e30f;
            mx0 = fmaxf(mx0, fmaxf(s[nt][0], s[nt][1]));
            mx1 = fmaxf(mx1, fmaxf(s[nt][2], s[nt][3]));
        }
        mx0 = fmaxf(mx0, __shfl_xor_sync(0xffffffffu, mx0, 1));
        mx0 = fmaxf(mx0, __shfl_xor_sync(0xffffffffu, mx0, 2));
        mx1 = fmaxf(mx1, __shfl_xor_sync(0xffffffffu, mx1, 1));
        mx1 = fmaxf(mx1, __shfl_xor_sync(0xffffffffu, mx1, 2));
        if (tig == 0) {
            pmax[wc * 64 + r0] = mx0;
            pmax[wc * 64 + r1] = mx1;
        }
        __syncthreads();

        // ---- combine max, exp -> P smem, partial sums ----
        float mold0 = Mrow[r0], mold1 = Mrow[r1];
        float mn0 = fmaxf(mold0, fmaxf(pmax[r0], pmax[64 + r0]));
        float mn1 = fmaxf(mold1, fmaxf(pmax[r1], pmax[64 + r1]));
        float sc0 = __expf(mold0 - mn0), sc1 = __expf(mold1 - mn1);
        float sum0 = 0.f, sum1 = 0.f;
#pragma unroll
        for (int nt = 0; nt < 4; nt++) {
            int c0 = wc * 32 + nt * 8 + 2 * tig;
            float p0 = __expf(s[nt][0] - mn0), p1 = __expf(s[nt][1] - mn0);
            float p2 = __expf(s[nt][2] - mn1), p3 = __expf(s[nt][3] - mn1);
            sum0 += p0 + p1; sum1 += p2 + p3;
            *(__half2*)(Ps + r0 * 72 + c0) = __floats2half2_rn(p0, p1);
            *(__half2*)(Ps + r1 * 72 + c0) = __floats2half2_rn(p2, p3);
        }
        sum0 += __shfl_xor_sync(0xffffffffu, sum0, 1);
        sum0 += __shfl_xor_sync(0xffffffffu, sum0, 2);
        sum1 += __shfl_xor_sync(0xffffffffu, sum1, 1);
        sum1 += __shfl_xor_sync(0xffffffffu, sum1, 2);
        if (tig == 0) {
            psum[wc * 64 + r0] = sum0;
            psum[wc * 64 + r1] = sum1;
        }
        __syncthreads();

        // ---- stats update (single writer per row), rescale O, PV ----
        if (wc == 0 && tig == 0) {
            Mrow[r0] = mn0;
            Lrow[r0] = Lrow[r0] * sc0 + psum[r0] + psum[64 + r0];
            Mrow[r1] = mn1;
            Lrow[r1] = Lrow[r1] * sc1 + psum[r1] + psum[64 + r1];
        }
#pragma unroll
        for (int nt = 0; nt < 8; nt++) {
            o[nt][0] *= sc0; o[nt][1] *= sc0;
            o[nt][2] *= sc1; o[nt][3] *= sc1;
        }
#pragma unroll
        for (int kc = 0; kc < 4; kc++) {
            uint32_t paf[4];
            ldsm4(paf, pbs + (qg * 16 + lr) * 144 + (2 * kc + lc) * 16);
#pragma unroll
            for (int jj = 0; jj < 4; jj++) {
                uint32_t bf[4];
                ldsm4t(bf, vbs + (kc * 16 + lr) * 272 + (wc * 8 + 2 * jj + lc) * 16);
                mma16(o[2 * jj],     paf, bf[0], bf[1]);
                mma16(o[2 * jj + 1], paf, bf[2], bf[3]);
            }
        }
        __syncthreads();
    }

    // epilogue
    float inv0 = 1.f / Lrow[r0], inv1 = 1.f / Lrow[r1];
#pragma unroll
    for (int t = 0; t < 8; t++) {
        int c0 = wc * 64 + t * 8 + 2 * tig;
        *(__half2*)(O + (qbase + r0) * 2048 + h * 128 + c0) =
            __floats2half2_rn(o[t][0] * inv0, o[t][1] * inv0);
        *(__half2*)(O + (qbase + r1) * 2048 + h * 128 + c0) =
            __floats2half2_rn(o[t][2] * inv1, o[t][3] * inv1);
    }
}

// ---------------- launcher -------------------------------------------------
extern "C" void kernel_launch(void* const* d_in, const int* in_sizes, int n_in,
                              void* d_out, int out_size)
{
    const float* x     = (const float*)d_in[0];
    const float* cosT  = (const float*)d_in[1];
    const float* sinT  = (const float*)d_in[2];
    const float* Wq_s  = (const float*)d_in[3];
    const float* qs_w  = (const float*)d_in[4];
    const float* Wkv_s = (const float*)d_in[5];
    const float* kvs_w = (const float*)d_in[6];
    const float* Wq_p  = (const float*)d_in[7];
    const float* Wkv_p = (const float*)d_in[8];
    const float* Wg_p  = (const float*)d_in[9];
    const float* Wo_p  = (const float*)d_in[10];
    const float* o_w   = (const float*)d_in[11];
    const float* Wo_s  = (const float*)d_in[12];
    float* out = (float*)d_out;

    float *qskvs, *o;
    __half *xh, *qsh, *kvsh, *qh, *kvh, *gatesh, *attnh, *oh;
    __half *wqkvs_h, *wqp_h, *wkvp_h, *wgp_h, *wop_h, *wos_h;
    cudaGetSymbolAddress((void**)&qskvs,  g_qskvs);
    cudaGetSymbolAddress((void**)&o,      g_o);
    cudaGetSymbolAddress((void**)&xh,     g_xh);
    cudaGetSymbolAddress((void**)&qsh,    g_qsh);
    cudaGetSymbolAddress((void**)&kvsh,   g_kvsh);
    cudaGetSymbolAddress((void**)&qh,     g_qh);
    cudaGetSymbolAddress((void**)&kvh,    g_kvh);
    cudaGetSymbolAddress((void**)&gatesh, g_gatesh);
    cudaGetSymbolAddress((void**)&attnh,  g_attnh);
    cudaGetSymbolAddress((void**)&oh,     g_oh);
    cudaGetSymbolAddress((void**)&wqkvs_h, g_wqkvs_h);
    cudaGetSymbolAddress((void**)&wqp_h,  g_wqp_h);
    cudaGetSymbolAddress((void**)&wkvp_h, g_wkvp_h);
    cudaGetSymbolAddress((void**)&wgp_h,  g_wgp_h);
    cudaGetSymbolAddress((void**)&wop_h,  g_wop_h);
    cudaGetSymbolAddress((void**)&wos_h,  g_wos_h);

    cudaFuncSetAttribute(flash64, cudaFuncAttributeMaxDynamicSharedMemorySize, F64_SMEM_BYTES);
    cudaFuncSetAttribute(gemm_h<0>, cudaFuncAttributeMaxDynamicSharedMemorySize, GH_SMEM_BYTES);
    cudaFuncSetAttribute(gemm_h<1>, cudaFuncAttributeMaxDynamicSharedMemorySize, GH_SMEM_BYTES);
    cudaFuncSetAttribute(gemm_h<2>, cudaFuncAttributeMaxDynamicSharedMemorySize, GH_SMEM_BYTES);
    cudaFuncSetAttribute(gemm_h<3>, cudaFuncAttributeMaxDynamicSharedMemorySize, GH_SMEM_BYTES);
    cudaFuncSetAttribute(gemm64, cudaFuncAttributeMaxDynamicSharedMemorySize, G64_SMEM_BYTES);

    cudaStream_t s1;
    cudaStreamCreateWithFlags(&s1, cudaStreamNonBlocking);
    cudaEvent_t evCvt, evGates;
    cudaEventCreateWithFlags(&evCvt, cudaEventDisableTiming);
    cudaEventCreateWithFlags(&evGates, cudaEventDisableTiming);

    dim3 blk(256);
    cvt_all<<<CV_BLOCKS, 256>>>(x, Wq_s, Wkv_s, Wq_p, Wkv_p, Wg_p, Wo_p, Wo_s,
                                xh, wqkvs_h, wqkvs_h + (size_t)D_CQ * HIDD,
                                wqp_h, wkvp_h, wgp_h, wop_h, wos_h);
    cudaEventRecord(evCvt, 0);

    cudaStreamWaitEvent(s1, evCvt, 0);
    gemm_h<1><<<dim3(2048 / 128, NTOK / 128), blk, GH_SMEM_BYTES, s1>>>(
        xh, wgp_h, gatesh, 2048, HIDD, 0, 0, 0);
    cudaEventRecord(evGates, s1);

    gemm64<<<dim3(D_QKVS / 128, NTOK / 64), dim3(128), G64_SMEM_BYTES>>>(
        xh, wqkvs_h, qskvs, D_QKVS, HIDD);
    rms2<<<dim3(NTOK, 2), 256>>>(qskvs, qs_w, kvs_w, D_CQ, D_CKV, D_QKVS, qsh, kvsh);
    gemm_h<2><<<dim3(2048 / 128, NTOK / 128), blk, GH_SMEM_BYTES>>>(
        qsh, wqp_h, qh, 2048, D_CQ, cosT, sinT, 0);

    cudaStreamWaitEvent(0, evGates, 0);
    gemm_h<3><<<dim3(4096 / 128, NTOK / 128), blk, GH_SMEM_BYTES>>>(
        kvsh, wkvp_h, kvh, 4096, D_CKV, cosT, sinT, gatesh);

    flash64<<<dim3(TSEQ / 64, NH, 2), blk, F64_SMEM_BYTES>>>(qh, kvh, attnh);

    gemm64<<<dim3(D_CO / 128, NTOK / 64), dim3(128), G64_SMEM_BYTES>>>(
        attnh, wop_h, o, D_CO, 2048);
    rms2<<<dim3(NTOK, 1), 256>>>(o, o_w, o_w, D_CO, D_CO, D_CO, oh, oh);
    gemm_h<0><<<dim3(HIDD / 128, NTOK / 128), blk, GH_SMEM_BYTES>>>(
        oh, wos_h, out, HIDD, D_CO, 0, 0, 0);
}

// round 17
// speedup vs baseline: 1.0645x; 1.0645x over previous
#include <cuda_runtime.h>
#include <cuda_fp16.h>
#include <math.h>
#include <stdint.h>

// ---------------- problem constants ----------------
#define NTOK 4096      // B*T
#define TSEQ 2048
#define HIDD 2048
#define NH   16
#define DHEAD 128
#define RROT 32
#define D_CQ 768
#define D_CKV 512
#define D_CO 512
#define D_QKVS 1280    // D_CQ + D_CKV
#define QK_SCALE 0.08838834764831845f  // 128^-0.5

// ---------------- scratch ----------------
__device__ float g_qskvs[(size_t)NTOK * D_QKVS];   // qs | kvs (fp32, pre-rms)
__device__ float g_o[(size_t)NTOK * D_CO];
__device__ __half g_xh[(size_t)NTOK * HIDD];
__device__ __half g_qsh[(size_t)NTOK * D_CQ];
__device__ __half g_kvsh[(size_t)NTOK * D_CKV];
__device__ __half g_qh[(size_t)NTOK * 2048];
__device__ __half g_kvh[(size_t)NTOK * 4096];   // k | v
__device__ __half g_gatesh[(size_t)NTOK * 2048];
__device__ __half g_attnh[(size_t)NTOK * 2048];
__device__ __half g_oh[(size_t)NTOK * D_CO];
__device__ __half g_wqkvs_h[(size_t)D_QKVS * HIDD];  // wqs | wkvs
__device__ __half g_wqp_h[(size_t)2048 * D_CQ];
__device__ __half g_wkvp_h[(size_t)4096 * D_CKV];
__device__ __half g_wgp_h[(size_t)2048 * HIDD];
__device__ __half g_wop_h[(size_t)D_CO * 2048];
__device__ __half g_wos_h[(size_t)HIDD * D_CO];

// ---------------- helpers ----------------
__device__ __forceinline__ uint32_t smem_u32(const void* p) {
    uint32_t a;
    asm("{ .reg .u64 t; cvta.to.shared.u64 t, %1; cvt.u32.u64 %0, t; }" : "=r"(a) : "l"(p));
    return a;
}
__device__ __forceinline__ void mma16(float c[4], const uint32_t a[4], uint32_t b0, uint32_t b1) {
    asm volatile(
        "mma.sync.aligned.m16n8k16.row.col.f32.f16.f16.f32 "
        "{%0,%1,%2,%3},{%4,%5,%6,%7},{%8,%9},{%0,%1,%2,%3};"
        : "+f"(c[0]), "+f"(c[1]), "+f"(c[2]), "+f"(c[3])
        : "r"(a[0]), "r"(a[1]), "r"(a[2]), "r"(a[3]), "r"(b0), "r"(b1));
}
__device__ __forceinline__ void ldsm4(uint32_t* r, uint32_t a) {
    asm volatile("ldmatrix.sync.aligned.m8n8.x4.shared.b16 {%0,%1,%2,%3}, [%4];"
        : "=r"(r[0]), "=r"(r[1]), "=r"(r[2]), "=r"(r[3]) : "r"(a));
}
__device__ __forceinline__ void ldsm4t(uint32_t* r, uint32_t a) {
    asm volatile("ldmatrix.sync.aligned.m8n8.x4.trans.shared.b16 {%0,%1,%2,%3}, [%4];"
        : "=r"(r[0]), "=r"(r[1]), "=r"(r[2]), "=r"(r[3]) : "r"(a));
}
__device__ __forceinline__ void cpa16(uint32_t saddr, const void* g) {
    asm volatile("cp.async.cg.shared.global [%0], [%1], 16;" :: "r"(saddr), "l"(g));
}
#define CPA_COMMIT() asm volatile("cp.async.commit_group;" ::: "memory")
#define CPA_WAIT(n)  asm volatile("cp.async.wait_group %0;" :: "n"(n) : "memory")
__device__ __forceinline__ uint32_t h2u(__half2 h) {
    uint32_t u;
    asm("mov.b32 %0, %1;" : "=r"(u) : "r"(*(uint32_t*)&h));
    return u;
}

// ---------------- fp32 -> fp16 converts ------------------------------------
// main: x | wqs | wkvs | wqp | wkvp | wgp
#define CV_P1 8388608u
#define CV_P2 (CV_P1 + 1572864u)
#define CV_P3 (CV_P2 + 1048576u)
#define CV_P4 (CV_P3 + 1572864u)
#define CV_P5 (CV_P4 + 2097152u)
#define CV_P6 (CV_P5 + 4194304u)
#define CV6_BLOCKS (CV_P6 / 1024)

__global__ void cvt6(
    const float* __restrict__ s0, const float* __restrict__ s1,
    const float* __restrict__ s2, const float* __restrict__ s3,
    const float* __restrict__ s4, const float* __restrict__ s5,
    __half* __restrict__ d0, __half* __restrict__ d1,
    __half* __restrict__ d2, __half* __restrict__ d3,
    __half* __restrict__ d4, __half* __restrict__ d5)
{
    uint32_t i = (blockIdx.x * 256 + threadIdx.x) * 4;
    const float* s; __half* d; uint32_t off;
    if      (i < CV_P1) { s = s0; d = d0; off = i; }
    else if (i < CV_P2) { s = s1; d = d1; off = i - CV_P1; }
    else if (i < CV_P3) { s = s2; d = d2; off = i - CV_P2; }
    else if (i < CV_P4) { s = s3; d = d3; off = i - CV_P3; }
    else if (i < CV_P5) { s = s4; d = d4; off = i - CV_P4; }
    else                { s = s5; d = d5; off = i - CV_P5; }
    float4 v = *(const float4*)(s + off);
    __half2* o = (__half2*)(d + off);
    o[0] = __floats2half2_rn(v.x, v.y);
    o[1] = __floats2half2_rn(v.z, v.w);
}

// tail: wop | wos (each 1048576 elements), off the critical path
__global__ void cvt2(const float* __restrict__ s0, const float* __restrict__ s1,
                     __half* __restrict__ d0, __half* __restrict__ d1)
{
    uint32_t i = (blockIdx.x * 256 + threadIdx.x) * 4;
    const float* s; __half* d; uint32_t off;
    if (i < 1048576u) { s = s0; d = d0; off = i; }
    else              { s = s1; d = d1; off = i - 1048576u; }
    float4 v = *(const float4*)(s + off);
    __half2* o = (__half2*)(d + off);
    o[0] = __floats2half2_rn(v.x, v.y);
    o[1] = __floats2half2_rn(v.z, v.w);
}

// ---------------- fp16 GEMM 128x128 (verified R8) --------------------------
#define GH_SMEM_BYTES (3 * 16384)

template <int MODE>
__global__ __launch_bounds__(256, 2) void gemm_h(
    const __half* __restrict__ A, const __half* __restrict__ B, void* __restrict__ Cv,
    int N, int K,
    const float* __restrict__ cosT, const float* __restrict__ sinT,
    const __half* __restrict__ gates)
{
    extern __shared__ char hsm[];
    const uint32_t shb = smem_u32(hsm);
    const int tid = threadIdx.x, lane = tid & 31, w = tid >> 5;
    const int g = lane >> 2, tig = lane & 3;
    const int wm = (w & 3) * 32, wn = (w >> 2) * 64;
    const int bm = blockIdx.y * 128, bn = blockIdx.x * 128;
    const int lr = lane & 15, lc = lane >> 4;

    float acc[2][8][4];
#pragma unroll
    for (int mt = 0; mt < 2; mt++)
#pragma unroll
        for (int nt = 0; nt < 8; nt++)
#pragma unroll
            for (int r = 0; r < 4; r++) acc[mt][nt][r] = 0.f;

    const int srow = tid >> 1, shalf = tid & 1;
    const __half* pa = A + (size_t)(bm + srow) * K + shalf * 16;
    const __half* pb = B + (size_t)(bn + srow) * K + shalf * 16;
    const uint32_t da0 = srow * 64 + ((((shalf * 2 + 0) + (srow >> 1)) & 3) << 4);
    const uint32_t da1 = srow * 64 + ((((shalf * 2 + 1) + (srow >> 1)) & 3) << 4);

    const int ntile = K >> 5;
#define GH_ISSUE(t) do {                                       \
        uint32_t _b = shb + ((t) % 3) * 16384;                 \
        const __half* _a = pa + (size_t)(t) * 32;              \
        const __half* _bb = pb + (size_t)(t) * 32;             \
        cpa16(_b + da0, _a);                                   \
        cpa16(_b + da1, _a + 8);                               \
        cpa16(_b + 8192 + da0, _bb);                           \
        cpa16(_b + 8192 + da1, _bb + 8);                       \
        CPA_COMMIT();                                          \
    } while (0)

    GH_ISSUE(0);
    GH_ISSUE(1);

    for (int i = 0; i < ntile; i++) {
        if (i < ntile - 1) { CPA_WAIT(1); } else { CPA_WAIT(0); }
        __syncthreads();
        if (i + 2 < ntile) GH_ISSUE(i + 2);
        const uint32_t base = shb + (i % 3) * 16384;
#pragma unroll
        for (int ks = 0; ks < 2; ks++) {
            const int cb = 2 * ks + lc;
            uint32_t af[2][4], bf[4][4];
#pragma unroll
            for (int mt = 0; mt < 2; mt++) {
                int r = wm + mt * 16 + lr;
                ldsm4(af[mt], base + r * 64 + (((cb + (r >> 1)) & 3) << 4));
            }
#pragma unroll
            for (int p = 0; p < 4; p++) {
                int r = wn + p * 16 + lr;
                ldsm4(bf[p], base + 8192 + r * 64 + (((cb + (r >> 1)) & 3) << 4));
            }
#pragma unroll
            for (int mt = 0; mt < 2; mt++)
#pragma unroll
                for (int nt = 0; nt < 8; nt++) {
                    int p = nt >> 1, s = nt & 1;
                    mma16(acc[mt][nt], af[mt], bf[p][s], bf[p][s + 2]);
                }
        }
        __syncthreads();
    }

    if ((MODE == 2 || (MODE == 3 && bn < 2048)) && wn == 0) {
#pragma unroll
        for (int mt = 0; mt < 2; mt++) {
            int r0 = bm + wm + mt * 16 + g;
            int t0 = r0 & (TSEQ - 1), t1 = (r0 + 8) & (TSEQ - 1);
#pragma unroll
            for (int nt = 0; nt < 2; nt++) {
                int d = nt * 8 + 2 * tig;
                float c0a = cosT[t0 * RROT + d],      c0b = cosT[t0 * RROT + d + 1];
                float c0c = cosT[t0 * RROT + d + 16], c0d = cosT[t0 * RROT + d + 17];
                float s0a = sinT[t0 * RROT + d],      s0b = sinT[t0 * RROT + d + 1];
                float s0c = sinT[t0 * RROT + d + 16], s0d = sinT[t0 * RROT + d + 17];
                float c1a = cosT[t1 * RROT + d],      c1b = cosT[t1 * RROT + d + 1];
                float c1c = cosT[t1 * RROT + d + 16], c1d = cosT[t1 * RROT + d + 17];
                float s1a = sinT[t1 * RROT + d],      s1b = sinT[t1 * RROT + d + 1];
                float s1c = sinT[t1 * RROT + d + 16], s1d = sinT[t1 * RROT + d + 17];
                float x, y;
                x = acc[mt][nt][0]; y = acc[mt][nt + 2][0];
                acc[mt][nt][0] = x * c0a - y * s0a; acc[mt][nt + 2][0] = y * c0c + x * s0c;
                x = acc[mt][nt][1]; y = acc[mt][nt + 2][1];
                acc[mt][nt][1] = x * c0b - y * s0b; acc[mt][nt + 2][1] = y * c0d + x * s0d;
                x = acc[mt][nt][2]; y = acc[mt][nt + 2][2];
                acc[mt][nt][2] = x * c1a - y * s1a; acc[mt][nt + 2][2] = y * c1c + x * s1c;
                x = acc[mt][nt][3]; y = acc[mt][nt + 2][3];
                acc[mt][nt][3] = x * c1b - y * s1b; acc[mt][nt + 2][3] = y * c1d + x * s1d;
            }
        }
    }
    if (MODE == 3 && bn >= 2048) {
#pragma unroll
        for (int mt = 0; mt < 2; mt++) {
            int r0 = bm + wm + mt * 16 + g;
#pragma unroll
            for (int nt = 0; nt < 8; nt++) {
                int cg = bn - 2048 + wn + nt * 8 + 2 * tig;
                __half2 ga = *(const __half2*)(gates + (size_t)r0 * 2048 + cg);
                __half2 gb = *(const __half2*)(gates + (size_t)(r0 + 8) * 2048 + cg);
                float g0 = __low2float(ga), g1 = __high2float(ga);
                float g2 = __low2float(gb), g3 = __high2float(gb);
                acc[mt][nt][0] *= g0 / (1.f + __expf(-g0));
                acc[mt][nt][1] *= g1 / (1.f + __expf(-g1));
                acc[mt][nt][2] *= g2 / (1.f + __expf(-g2));
                acc[mt][nt][3] *= g3 / (1.f + __expf(-g3));
            }
        }
    }

#pragma unroll
    for (int mt = 0; mt < 2; mt++) {
        int r0 = bm + wm + mt * 16 + g;
#pragma unroll
        for (int nt = 0; nt < 8; nt++) {
            int c0 = bn + wn + nt * 8 + 2 * tig;
            if (MODE == 0) {
                float* C = (float*)Cv;
                *(float2*)(C + (size_t)r0 * N + c0)       = make_float2(acc[mt][nt][0], acc[mt][nt][1]);
                *(float2*)(C + (size_t)(r0 + 8) * N + c0) = make_float2(acc[mt][nt][2], acc[mt][nt][3]);
            } else {
                __half* C = (__half*)Cv;
                *(__half2*)(C + (size_t)r0 * N + c0)       = __floats2half2_rn(acc[mt][nt][0], acc[mt][nt][1]);
                *(__half2*)(C + (size_t)(r0 + 8) * N + c0) = __floats2half2_rn(acc[mt][nt][2], acc[mt][nt][3]);
            }
        }
    }
}

// ---------------- fp16 GEMM 64x128, 128 threads, 4 CTAs/SM -----------------
#define G64_STG 12288
#define G64_SMEM_BYTES (3 * G64_STG)

__global__ __launch_bounds__(128, 4) void gemm64(
    const __half* __restrict__ A, const __half* __restrict__ B, float* __restrict__ C,
    int N, int K)
{
    extern __shared__ char hsm[];
    const uint32_t shb = smem_u32(hsm);
    const int tid = threadIdx.x, lane = tid & 31, w = tid >> 5;
    const int g = lane >> 2, tig = lane & 3;
    const int wm = (w & 1) * 32, wn = (w >> 1) * 64;
    const int bm = blockIdx.y * 64, bn = blockIdx.x * 128;
    const int lr = lane & 15, lc = lane >> 4;

    float acc[2][8][4];
#pragma unroll
    for (int mt = 0; mt < 2; mt++)
#pragma unroll
        for (int nt = 0; nt < 8; nt++)
#pragma unroll
            for (int r = 0; r < 4; r++) acc[mt][nt][r] = 0.f;

    const int ntile = K >> 5;
#define G64_ISSUE(t) do {                                                        \
        uint32_t _b = shb + ((t) % 3) * G64_STG;                                 \
        _Pragma("unroll")                                                        \
        for (int _j = 0; _j < 6; _j++) {                                         \
            int _f = _j * 128 + tid;                                             \
            int _r = _f >> 2, _c = _f & 3;                                       \
            uint32_t _d = _b + _r * 64 + (((_c + (_r >> 1)) & 3) << 4);          \
            const __half* _g = (_r < 64)                                         \
                ? A + (size_t)(bm + _r) * K + (size_t)(t) * 32 + _c * 8          \
                : B + (size_t)(bn + _r - 64) * K + (size_t)(t) * 32 + _c * 8;    \
            cpa16(_d, _g);                                                       \
        }                                                                        \
        CPA_COMMIT();                                                            \
    } while (0)

    G64_ISSUE(0);
    G64_ISSUE(1);

    for (int i = 0; i < ntile; i++) {
        if (i < ntile - 1) { CPA_WAIT(1); } else { CPA_WAIT(0); }
        __syncthreads();
        if (i + 2 < ntile) G64_ISSUE(i + 2);
        const uint32_t base = shb + (i % 3) * G64_STG;
#pragma unroll
        for (int ks = 0; ks < 2; ks++) {
            const int cb = 2 * ks + lc;
            uint32_t af[2][4], bf[4][4];
#pragma unroll
            for (int mt = 0; mt < 2; mt++) {
                int r = wm + mt * 16 + lr;
                ldsm4(af[mt], base + r * 64 + (((cb + (r >> 1)) & 3) << 4));
            }
#pragma unroll
            for (int p = 0; p < 4; p++) {
                int r = 64 + wn + p * 16 + lr;
                ldsm4(bf[p], base + r * 64 + (((cb + (r >> 1)) & 3) << 4));
            }
#pragma unroll
            for (int mt = 0; mt < 2; mt++)
#pragma unroll
                for (int nt = 0; nt < 8; nt++) {
                    int p = nt >> 1, s = nt & 1;
                    mma16(acc[mt][nt], af[mt], bf[p][s], bf[p][s + 2]);
                }
        }
        __syncthreads();
    }

#pragma unroll
    for (int mt = 0; mt < 2; mt++) {
        int r0 = bm + wm + mt * 16 + g;
#pragma unroll
        for (int nt = 0; nt < 8; nt++) {
            int c0 = bn + wn + nt * 8 + 2 * tig;
            *(float2*)(C + (size_t)r0 * N + c0)       = make_float2(acc[mt][nt][0], acc[mt][nt][1]);
            *(float2*)(C + (size_t)(r0 + 8) * N + c0) = make_float2(acc[mt][nt][2], acc[mt][nt][3]);
        }
    }
}

// ---------------- RMSNorm (vectorized, paired segments) --------------------
__global__ void rms2(const float* __restrict__ X,
                     const float* __restrict__ w0, const float* __restrict__ w1,
                     int D0, int D1, int strideX,
                     __half* __restrict__ H0, __half* __restrict__ H1)
{
    __shared__ float red[8];
    const int row = blockIdx.x, tid = threadIdx.x;
    const int lane = tid & 31, wid = tid >> 5;
    const int which = blockIdx.y;
    const int D = which ? D1 : D0;
    const float* w = which ? w1 : w0;
    const float4* x = (const float4*)(X + (size_t)row * strideX + (which ? D0 : 0));
    __half* hh = (which ? H1 : H0) + (size_t)row * D;
    const int D4 = D >> 2;
    float ss = 0.f;
    for (int i = tid; i < D4; i += 256) {
        float4 v = x[i];
        ss += v.x * v.x + v.y * v.y + v.z * v.z + v.w * v.w;
    }
#pragma unroll
    for (int m = 16; m > 0; m >>= 1) ss += __shfl_xor_sync(0xffffffff, ss, m);
    if (lane == 0) red[wid] = ss;
    __syncthreads();
    float tot = 0.f;
#pragma unroll
    for (int j = 0; j < 8; j++) tot += red[j];
    float inv = rsqrtf(tot / (float)D + 1e-6f);
    for (int i = tid; i < D4; i += 256) {
        float4 v = x[i];
        float4 ww = *(const float4*)(w + i * 4);
        __half2* dst = (__half2*)(hh + i * 4);
        dst[0] = __floats2half2_rn(ww.x * (v.x * inv), ww.y * (v.y * inv));
        dst[1] = __floats2half2_rn(ww.z * (v.z * inv), ww.w * (v.w * inv));
    }
}

// ---------------- flash attention (R13 design + 3-stage KV pipeline) -------
// 128 q x 64 k tiles, 256 threads; warp tile 16q x 64k; register softmax.
#define FH_QB 34816u
#define FH_KVB 17408u
#define FH_SMEM_BYTES (FH_QB + 6 * FH_KVB)    // 139264

__global__ __launch_bounds__(256) void flash_h16(
    const __half* __restrict__ Qh, const __half* __restrict__ KVh, __half* __restrict__ O)
{
    extern __shared__ __half sh2[];
    const uint32_t qbs = smem_u32(sh2);

    const int qt = (int)gridDim.x - 1 - blockIdx.x;   // LPT
    const int h = blockIdx.y, b = blockIdx.z;
    const int tid = threadIdx.x, lane = tid & 31, w = tid >> 5;
    const int g = lane >> 2, tig = lane & 3;
    const int lr = lane & 15, lc = lane >> 4;
    const int qrow0 = w * 16;
    const size_t qbase = (size_t)b * TSEQ + qt * 128;
    const size_t kvrow = (size_t)b * TSEQ;

#define FH_KV_ISSUE(kt) do {                                                     \
        const uint32_t _kb = qbs + FH_QB + ((kt) % 3) * (2 * FH_KVB);            \
        const __half* _base = KVh + (kvrow + (size_t)(kt) * 64) * 4096 + h * 128;\
        _Pragma("unroll")                                                        \
        for (int _j = 0; _j < 4; _j++) {                                         \
            int _f = tid * 4 + _j;                                               \
            int _r = _f >> 4, _c = _f & 15;                                      \
            uint32_t _d = _r * 272 + _c * 16;                                    \
            cpa16(_kb + _d,          _base + (size_t)_r * 4096 + _c * 8);        \
            cpa16(_kb + FH_KVB + _d, _base + (size_t)_r * 4096 + 2048 + _c * 8); \
        }                                                                        \
        CPA_COMMIT();                                                            \
    } while (0)

    // stage Q (group) + first two KV tiles (nkt >= 2 always)
#pragma unroll
    for (int j = 0; j < 8; j++) {
        int f = tid * 8 + j;
        int r = f >> 4, c = f & 15;
        cpa16(qbs + r * 272 + c * 16, Qh + (qbase + r) * 2048 + h * 128 + c * 8);
    }
    CPA_COMMIT();
    FH_KV_ISSUE(0);
    FH_KV_ISSUE(1);
    CPA_WAIT(2);        // Q complete
    __syncthreads();

    uint32_t qf[8][4];
#pragma unroll
    for (int kc = 0; kc < 8; kc++)
        ldsm4(qf[kc], qbs + (qrow0 + lr) * 272 + (2 * kc + lc) * 16);

    float m0 = -1e30f, m1 = -1e30f, l0 = 0.f, l1 = 0.f;
    float o[16][4];
#pragma unroll
    for (int nt = 0; nt < 16; nt++)
#pragma unroll
        for (int r = 0; r < 4; r++) o[nt][r] = 0.f;

    const int nkt = 2 * qt + 2;
    for (int kt = 0; kt < nkt; kt++) {
        if (kt + 2 < nkt)      { FH_KV_ISSUE(kt + 2); CPA_WAIT(2); }
        else if (kt + 1 < nkt) { CPA_WAIT(1); }
        else                   { CPA_WAIT(0); }
        __syncthreads();
        const uint32_t kbs = qbs + FH_QB + (kt % 3) * (2 * FH_KVB);
        const uint32_t vbs = kbs + FH_KVB;

        float s[8][4];
#pragma unroll
        for (int nt = 0; nt < 8; nt++)
#pragma unroll
            for (int r = 0; r < 4; r++) s[nt][r] = 0.f;
#pragma unroll
        for (int ks = 0; ks < 8; ks++) {
            uint32_t bf[4][4];
#pragma unroll
            for (int p = 0; p < 4; p++)
                ldsm4(bf[p], kbs + (p * 16 + lr) * 272 + (2 * ks + lc) * 16);
#pragma unroll
            for (int nt = 0; nt < 8; nt++) {
                int p = nt >> 1, ss = nt & 1;
                mma16(s[nt], qf[ks], bf[p][ss], bf[p][ss + 2]);
            }
        }

        const int qg0 = qt * 128 + qrow0 + g, qg1 = qg0 + 8;
        float mx0 = -1e30f, mx1 = -1e30f;
#pragma unroll
        for (int nt = 0; nt < 8; nt++) {
            int kg0 = kt * 64 + nt * 8 + 2 * tig, kg1 = kg0 + 1;
            s[nt][0] = (kg0 <= qg0) ? s[nt][0] * QK_SCALE : -1e30f;
            s[nt][1] = (kg1 <= qg0) ? s[nt][1] * QK_SCALE : -1e30f;
            s[nt][2] = (kg0 <= qg1) ? s[nt][2] * QK_SCALE : -1e30f;
            s[nt][3] = (kg1 <= qg1) ? s[nt][3] * QK_SCALE : -1e30f;
            mx0 = fmaxf(mx0, fmaxf(s[nt][0], s[nt][1]));
            mx1 = fmaxf(mx1, fmaxf(s[nt][2], s[nt][3]));
        }
        mx0 = fmaxf(mx0, __shfl_xor_sync(0xffffffffu, mx0, 1));
        mx0 = fmaxf(mx0, __shfl_xor_sync(0xffffffffu, mx0, 2));
        mx1 = fmaxf(mx1, __shfl_xor_sync(0xffffffffu, mx1, 1));
        mx1 = fmaxf(mx1, __shfl_xor_sync(0xffffffffu, mx1, 2));
        float nm0 = fmaxf(m0, mx0), nm1 = fmaxf(m1, mx1);
        float sc0 = __expf(m0 - nm0), sc1 = __expf(m1 - nm1);
        m0 = nm0; m1 = nm1;

        float sum0 = 0.f, sum1 = 0.f;
        uint32_t pa[8][2];
#pragma unroll
        for (int nt = 0; nt < 8; nt++) {
            float p0 = __expf(s[nt][0] - nm0), p1 = __expf(s[nt][1] - nm0);
            float p2 = __expf(s[nt][2] - nm1), p3 = __expf(s[nt][3] - nm1);
            sum0 += p0 + p1; sum1 += p2 + p3;
            pa[nt][0] = h2u(__floats2half2_rn(p0, p1));
            pa[nt][1] = h2u(__floats2half2_rn(p2, p3));
        }
        sum0 += __shfl_xor_sync(0xffffffffu, sum0, 1);
        sum0 += __shfl_xor_sync(0xffffffffu, sum0, 2);
        sum1 += __shfl_xor_sync(0xffffffffu, sum1, 1);
        sum1 += __shfl_xor_sync(0xffffffffu, sum1, 2);
        l0 = l0 * sc0 + sum0;
        l1 = l1 * sc1 + sum1;

#pragma unroll
        for (int nt = 0; nt < 16; nt++) {
            o[nt][0] *= sc0; o[nt][1] *= sc0;
            o[nt][2] *= sc1; o[nt][3] *= sc1;
        }
#pragma unroll
        for (int kc = 0; kc < 4; kc++) {
            uint32_t paf[4] = { pa[2 * kc][0], pa[2 * kc][1],
                                pa[2 * kc + 1][0], pa[2 * kc + 1][1] };
#pragma unroll
            for (int j = 0; j < 8; j++) {
                uint32_t bf[4];
                ldsm4t(bf, vbs + (kc * 16 + lr) * 272 + (2 * j + lc) * 16);
                mma16(o[2 * j],     paf, bf[0], bf[1]);
                mma16(o[2 * j + 1], paf, bf[2], bf[3]);
            }
        }
        __syncthreads();   // all warps done reading buf (kt%3) before re-stage
    }

    float inv0 = 1.f / l0, inv1 = 1.f / l1;
#pragma unroll
    for (int nt = 0; nt < 16; nt++) {
        int c0 = nt * 8 + 2 * tig;
        *(__half2*)(O + (qbase + qrow0 + g) * 2048 + h * 128 + c0) =
            __floats2half2_rn(o[nt][0] * inv0, o[nt][1] * inv0);
        *(__half2*)(O + (qbase + qrow0 + g + 8) * 2048 + h * 128 + c0) =
            __floats2half2_rn(o[nt][2] * inv1, o[nt][3] * inv1);
    }
}

// ---------------- launcher -------------------------------------------------
extern "C" void kernel_launch(void* const* d_in, const int* in_sizes, int n_in,
                              void* d_out, int out_size)
{
    const float* x     = (const float*)d_in[0];
    const float* cosT  = (const float*)d_in[1];
    const float* sinT  = (const float*)d_in[2];
    const float* Wq_s  = (const float*)d_in[3];
    const float* qs_w  = (const float*)d_in[4];
    const float* Wkv_s = (const float*)d_in[5];
    const float* kvs_w = (const float*)d_in[6];
    const float* Wq_p  = (const float*)d_in[7];
    const float* Wkv_p = (const float*)d_in[8];
    const float* Wg_p  = (const float*)d_in[9];
    const float* Wo_p  = (const float*)d_in[10];
    const float* o_w   = (const float*)d_in[11];
    const float* Wo_s  = (const float*)d_in[12];
    float* out = (float*)d_out;

    float *qskvs, *o;
    __half *xh, *qsh, *kvsh, *qh, *kvh, *gatesh, *attnh, *oh;
    __half *wqkvs_h, *wqp_h, *wkvp_h, *wgp_h, *wop_h, *wos_h;
    cudaGetSymbolAddress((void**)&qskvs,  g_qskvs);
    cudaGetSymbolAddress((void**)&o,      g_o);
    cudaGetSymbolAddress((void**)&xh,     g_xh);
    cudaGetSymbolAddress((void**)&qsh,    g_qsh);
    cudaGetSymbolAddress((void**)&kvsh,   g_kvsh);
    cudaGetSymbolAddress((void**)&qh,     g_qh);
    cudaGetSymbolAddress((void**)&kvh,    g_kvh);
    cudaGetSymbolAddress((void**)&gatesh, g_gatesh);
    cudaGetSymbolAddress((void**)&attnh,  g_attnh);
    cudaGetSymbolAddress((void**)&oh,     g_oh);
    cudaGetSymbolAddress((void**)&wqkvs_h, g_wqkvs_h);
    cudaGetSymbolAddress((void**)&wqp_h,  g_wqp_h);
    cudaGetSymbolAddress((void**)&wkvp_h, g_wkvp_h);
    cudaGetSymbolAddress((void**)&wgp_h,  g_wgp_h);
    cudaGetSymbolAddress((void**)&wop_h,  g_wop_h);
    cudaGetSymbolAddress((void**)&wos_h,  g_wos_h);

    cudaFuncSetAttribute(flash_h16, cudaFuncAttributeMaxDynamicSharedMemorySize, FH_SMEM_BYTES);
    cudaFuncSetAttribute(gemm_h<0>, cudaFuncAttributeMaxDynamicSharedMemorySize, GH_SMEM_BYTES);
    cudaFuncSetAttribute(gemm_h<1>, cudaFuncAttributeMaxDynamicSharedMemorySize, GH_SMEM_BYTES);
    cudaFuncSetAttribute(gemm_h<2>, cudaFuncAttributeMaxDynamicSharedMemorySize, GH_SMEM_BYTES);
    cudaFuncSetAttribute(gemm_h<3>, cudaFuncAttributeMaxDynamicSharedMemorySize, GH_SMEM_BYTES);
    cudaFuncSetAttribute(gemm64, cudaFuncAttributeMaxDynamicSharedMemorySize, G64_SMEM_BYTES);

    cudaStream_t s1;
    cudaStreamCreateWithFlags(&s1, cudaStreamNonBlocking);
    cudaEvent_t evCvt, evGates;
    cudaEventCreateWithFlags(&evCvt, cudaEventDisableTiming);
    cudaEventCreateWithFlags(&evGates, cudaEventDisableTiming);

    dim3 blk(256);
    // tail weights (wop, wos) convert off the critical path on s1
    cvt2<<<2048, 256, 0, s1>>>(Wo_p, Wo_s, wop_h, wos_h);
    cvt6<<<CV6_BLOCKS, 256>>>(x, Wq_s, Wkv_s, Wq_p, Wkv_p, Wg_p,
                              xh, wqkvs_h, wqkvs_h + (size_t)D_CQ * HIDD,
                              wqp_h, wkvp_h, wgp_h);
    cudaEventRecord(evCvt, 0);

    cudaStreamWaitEvent(s1, evCvt, 0);
    gemm_h<1><<<dim3(2048 / 128, NTOK / 128), blk, GH_SMEM_BYTES, s1>>>(
        xh, wgp_h, gatesh, 2048, HIDD, 0, 0, 0);
    cudaEventRecord(evGates, s1);

    gemm64<<<dim3(D_QKVS / 128, NTOK / 64), dim3(128), G64_SMEM_BYTES>>>(
        xh, wqkvs_h, qskvs, D_QKVS, HIDD);
    rms2<<<dim3(NTOK, 2), 256>>>(qskvs, qs_w, kvs_w, D_CQ, D_CKV, D_QKVS, qsh, kvsh);
    gemm_h<2><<<dim3(2048 / 128, NTOK / 128), blk, GH_SMEM_BYTES>>>(
        qsh, wqp_h, qh, 2048, D_CQ, cosT, sinT, 0);

    cudaStreamWaitEvent(0, evGates, 0);
    gemm_h<3><<<dim3(4096 / 128, NTOK / 128), blk, GH_SMEM_BYTES>>>(
        kvsh, wkvp_h, kvh, 4096, D_CKV, cosT, sinT, gatesh);

    flash_h16<<<dim3(TSEQ / 128, NH, 2), blk, FH_SMEM_BYTES>>>(qh, kvh, attnh);

    gemm64<<<dim3(D_CO / 128, NTOK / 64), dim3(128), G64_SMEM_BYTES>>>(
        attnh, wop_h, o, D_CO, 2048);
    rms2<<<dim3(NTOK, 1), 256>>>(o, o_w, o_w, D_CO, D_CO, D_CO, oh, oh);
    gemm_h<0><<<dim3(HIDD / 128, NTOK / 128), blk, GH_SMEM_BYTES>>>(
        oh, wos_h, out, HIDD, D_CO, 0, 0, 0);
}